// round 13
// baseline (speedup 1.0000x reference)
#include <cuda_runtime.h>
#include <cuda_fp16.h>
#include <cstdint>

// Problem: [B=8, C=3, N=1024, D=1024]
#define BCD    24
#define NPTS   1024
#define KDIM   1024

#define BM     128
#define BN     128
#define BKH    64              // k halves per stage (128 bytes/row)
#define NSTAGE 3
#define NKITER (KDIM / BKH)    // 16
#define ROWB   128             // smem bytes per row
#define A_BYTES (BM * ROWB)    // 16384
#define STAGE_BYTES (2 * A_BYTES)            // 32768
#define DSMEM_BYTES (NSTAGE * STAGE_BYTES)   // 98304

#define NCH    6               // pipeline chunks
#define CH     (BCD / NCH)     // 4 slices per chunk

// ---------------- scratch ----------------
__device__ __half g_xh[(size_t)BCD * NPTS * KDIM];
__device__ __half g_yh[(size_t)BCD * NPTS * KDIM];
__device__ float g_x2[BCD * NPTS];
__device__ float g_y2[BCD * NPTS];
__device__ int   g_rowmin[BCD * NPTS];
__device__ int   g_colmin[BCD * NPTS];

// ---------------- streams/events (static init: before harness checkpoints) ----
struct HdStreams {
    cudaStream_t gs[NCH];
    cudaEvent_t ev[NCH];
    cudaEvent_t done[NCH];
    HdStreams() {
        for (int i = 0; i < NCH; i++) {
            cudaStreamCreateWithFlags(&gs[i], cudaStreamNonBlocking);
            cudaEventCreateWithFlags(&ev[i], cudaEventDisableTiming);
            cudaEventCreateWithFlags(&done[i], cudaEventDisableTiming);
        }
    }
};
static HdStreams hds;

// ---------------- helpers ----------------
__device__ __forceinline__ uint32_t smem_u32(const void* p) {
    uint32_t a;
    asm("{ .reg .u64 t; cvta.to.shared.u64 t, %1; cvt.u32.u64 %0, t; }" : "=r"(a) : "l"(p));
    return a;
}
__device__ __forceinline__ void cp16(uint32_t dst, const void* src) {
    asm volatile("cp.async.cg.shared.global [%0], [%1], 16;" :: "r"(dst), "l"(src));
}
__device__ __forceinline__ void cp_commit() {
    asm volatile("cp.async.commit_group;" ::: "memory");
}
// 128B-row XOR swizzle: chunk c (16B) of row r -> c ^ (r & 7).
__device__ __forceinline__ uint32_t swz(int row, int c) {
    return (uint32_t)(row * ROWB + ((c ^ (row & 7)) << 4));
}
#define LDSM4(r0, r1, r2, r3, addr)                                          \
    asm volatile("ldmatrix.sync.aligned.m8n8.x4.shared.b16 {%0,%1,%2,%3}, [%4];" \
                 : "=r"(r0), "=r"(r1), "=r"(r2), "=r"(r3) : "r"(addr))
#define MMA16816(c, a, b)                                                    \
    asm volatile("mma.sync.aligned.m16n8k16.row.col.f32.f16.f16.f32 "        \
                 "{%0,%1,%2,%3}, {%4,%5,%6,%7}, {%8,%9}, {%0,%1,%2,%3};"     \
                 : "+f"((c)[0]), "+f"((c)[1]), "+f"((c)[2]), "+f"((c)[3])    \
                 : "r"((a)[0]), "r"((a)[1]), "r"((a)[2]), "r"((a)[3]),       \
                   "r"((b)[0]), "r"((b)[1]))

// ---------------- convert + norms + init for one chunk of CH slices ----------
// grid = (CH*NPTS/2, 2); block = 256 = 2 rows x 128 threads.
__global__ void hd_convert_norms(const float* __restrict__ x, const float* __restrict__ y,
                                 float* __restrict__ out, int bc0) {
    __shared__ float part[8];
    int tid = threadIdx.x;

    // Init this chunk's min arrays (2 entries per x-block, y==0 slice only).
    if (blockIdx.y == 0 && tid < 2) {
        int i = bc0 * NPTS + blockIdx.x * 2 + tid;
        g_rowmin[i] = 0x7F800000;
        g_colmin[i] = 0x7F800000;
        if (bc0 == 0 && blockIdx.x == 0 && tid == 0) out[0] = 0.0f;
    }

    size_t base = (size_t)bc0 * NPTS * KDIM + (size_t)blockIdx.x * 2048 + (size_t)tid * 8;
    const float* src = blockIdx.y ? y : x;
    __half* dst = blockIdx.y ? g_yh : g_xh;
    float* nrm = blockIdx.y ? g_y2 : g_x2;

    float4 v0 = *(const float4*)(src + base);
    float4 v1 = *(const float4*)(src + base + 4);
    __half2 h0 = __floats2half2_rn(v0.x, v0.y);
    __half2 h1 = __floats2half2_rn(v0.z, v0.w);
    __half2 h2 = __floats2half2_rn(v1.x, v1.y);
    __half2 h3 = __floats2half2_rn(v1.z, v1.w);
    uint4 o;
    o.x = *(uint32_t*)&h0; o.y = *(uint32_t*)&h1;
    o.z = *(uint32_t*)&h2; o.w = *(uint32_t*)&h3;
    *(uint4*)(dst + base) = o;

    float s = 0.0f;
    {
        float2 f;
        f = __half22float2(h0); s += f.x * f.x + f.y * f.y;
        f = __half22float2(h1); s += f.x * f.x + f.y * f.y;
        f = __half22float2(h2); s += f.x * f.x + f.y * f.y;
        f = __half22float2(h3); s += f.x * f.x + f.y * f.y;
    }
    #pragma unroll
    for (int off = 16; off > 0; off >>= 1)
        s += __shfl_down_sync(0xFFFFFFFFu, s, off);
    if ((tid & 31) == 0) part[tid >> 5] = s;
    __syncthreads();
    if (tid < 2) {
        float t = part[tid * 4] + part[tid * 4 + 1] + part[tid * 4 + 2] + part[tid * 4 + 3];
        nrm[bc0 * NPTS + blockIdx.x * 2 + tid] = t;
    }
}

// ---------------- stage loader ----------------
__device__ __forceinline__ void load_stage(int it, int tid, uint32_t sbase,
                                           const __half* __restrict__ gA,
                                           const __half* __restrict__ gB) {
    if (it < NKITER) {
        uint32_t sb = sbase + (it % NSTAGE) * STAGE_BYTES;
        int k0 = it * BKH;
        #pragma unroll
        for (int t = 0; t < 4; t++) {
            int idx = tid + t * 256;          // 0..1023
            int row = idx >> 3;               // 0..127
            int c = idx & 7;                  // 16B chunk (8 per row)
            cp16(sb + swz(row, c),           gA + (size_t)row * KDIM + k0 + c * 8);
            cp16(sb + A_BYTES + swz(row, c), gB + (size_t)row * KDIM + k0 + c * 8);
        }
    }
    cp_commit();
}

// ---------------- main MMA GEMM + fused min epilogue (R6 body) ----------------
__global__ void __launch_bounds__(256, 2)
hd_gemm_mma(int bc0) {
    extern __shared__ char smem[];
    __shared__ float sx2[BM], sy2[BN];
    __shared__ int sminr[BM], sminc[BN];

    int tid = threadIdx.x, lane = tid & 31, wid = tid >> 5;
    int warp_m = wid & 3, warp_n = wid >> 2;     // 4x2 warps, warp tile 32x64
    int bc = bc0 + blockIdx.z, nblk = blockIdx.y * BM, mblk = blockIdx.x * BN;
    const __half* gA = g_xh + ((size_t)bc * NPTS + nblk) * KDIM;
    const __half* gB = g_yh + ((size_t)bc * NPTS + mblk) * KDIM;
    uint32_t sbase = smem_u32(smem);

    if (tid < BM) {
        sx2[tid] = g_x2[bc * NPTS + nblk + tid];
        sy2[tid] = g_y2[bc * NPTS + mblk + tid];
        sminr[tid] = 0x7F800000;
        sminc[tid] = 0x7F800000;
    }

    float acc[2][8][4];
    #pragma unroll
    for (int mt = 0; mt < 2; mt++)
        #pragma unroll
        for (int nt = 0; nt < 8; nt++)
            #pragma unroll
            for (int e = 0; e < 4; e++) acc[mt][nt][e] = 0.0f;

    load_stage(0, tid, sbase, gA, gB);
    load_stage(1, tid, sbase, gA, gB);

    int lr = lane & 7, grp = lane >> 3;
    int arow0 = warp_m * 32 + lr + ((grp & 1) << 3);
    int brow0 = warp_n * 64 + lr + ((grp >> 1) << 3);
    int ac_x = grp >> 1;
    int bc_x = grp & 1;

    for (int i = 0; i < NKITER; i++) {
        asm volatile("cp.async.wait_group 1;" ::: "memory");
        __syncthreads();
        load_stage(i + 2, tid, sbase, gA, gB);
        uint32_t sA = sbase + (i % NSTAGE) * STAGE_BYTES;
        uint32_t sB = sA + A_BYTES;
        #pragma unroll
        for (int ks = 0; ks < 4; ks++) {
            uint32_t a[2][4], b[8][2];
            #pragma unroll
            for (int mt = 0; mt < 2; mt++) {
                int row = arow0 + mt * 16;
                uint32_t addr = sA + swz(row, ks * 2 + ac_x);
                LDSM4(a[mt][0], a[mt][1], a[mt][2], a[mt][3], addr);
            }
            #pragma unroll
            for (int bt = 0; bt < 4; bt++) {
                int row = brow0 + bt * 16;
                uint32_t addr = sB + swz(row, ks * 2 + bc_x);
                uint32_t r0, r1, r2, r3;
                LDSM4(r0, r1, r2, r3, addr);
                b[bt * 2][0] = r0;     b[bt * 2][1] = r1;
                b[bt * 2 + 1][0] = r2; b[bt * 2 + 1][1] = r3;
            }
            #pragma unroll
            for (int mt = 0; mt < 2; mt++)
                #pragma unroll
                for (int nt = 0; nt < 8; nt++)
                    MMA16816(acc[mt][nt], a[mt], b[nt]);
        }
    }

    // ---- fused epilogue: d2 + row/col mins ----
    int g = lane >> 2, l = lane & 3;
    float xr[4], yc[16];
    #pragma unroll
    for (int r = 0; r < 4; r++)
        xr[r] = sx2[warp_m * 32 + (r >> 1) * 16 + ((r & 1) << 3) + g];
    #pragma unroll
    for (int c = 0; c < 16; c++)
        yc[c] = sy2[warp_n * 64 + (c >> 1) * 8 + l * 2 + (c & 1)];

    float rmin[4], cmin[16];
    #pragma unroll
    for (int r = 0; r < 4; r++) rmin[r] = 3.4e38f;
    #pragma unroll
    for (int c = 0; c < 16; c++) cmin[c] = 3.4e38f;

    #pragma unroll
    for (int mt = 0; mt < 2; mt++)
        #pragma unroll
        for (int nt = 0; nt < 8; nt++)
            #pragma unroll
            for (int e = 0; e < 4; e++) {
                int rid = mt * 2 + (e >> 1);
                int cid = nt * 2 + (e & 1);
                float d2 = fmaxf(xr[rid] + yc[cid] - 2.0f * acc[mt][nt][e], 0.0f);
                rmin[rid] = fminf(rmin[rid], d2);
                cmin[cid] = fminf(cmin[cid], d2);
            }

    #pragma unroll
    for (int r = 0; r < 4; r++) {
        rmin[r] = fminf(rmin[r], __shfl_xor_sync(0xFFFFFFFFu, rmin[r], 1));
        rmin[r] = fminf(rmin[r], __shfl_xor_sync(0xFFFFFFFFu, rmin[r], 2));
    }
    #pragma unroll
    for (int c = 0; c < 16; c++) {
        cmin[c] = fminf(cmin[c], __shfl_xor_sync(0xFFFFFFFFu, cmin[c], 4));
        cmin[c] = fminf(cmin[c], __shfl_xor_sync(0xFFFFFFFFu, cmin[c], 8));
        cmin[c] = fminf(cmin[c], __shfl_xor_sync(0xFFFFFFFFu, cmin[c], 16));
    }
    if (l == 0) {
        #pragma unroll
        for (int r = 0; r < 4; r++)
            atomicMin(&sminr[warp_m * 32 + (r >> 1) * 16 + ((r & 1) << 3) + g],
                      __float_as_int(rmin[r]));
    }
    if (g == 0) {
        #pragma unroll
        for (int c = 0; c < 16; c++)
            atomicMin(&sminc[warp_n * 64 + (c >> 1) * 8 + l * 2 + (c & 1)],
                      __float_as_int(cmin[c]));
    }
    __syncthreads();
    if (tid < BM) {
        atomicMin(&g_rowmin[bc * NPTS + nblk + tid], sminr[tid]);
        atomicMin(&g_colmin[bc * NPTS + mblk + tid], sminc[tid]);
    }
}

// ---------------- final reduction: one block per (b,c) ----------------
__global__ void hd_reduce_kernel(float* __restrict__ out) {
    __shared__ float red[256];
    int bc = blockIdx.x, tid = threadIdx.x;
    float m = 0.0f;
    for (int i = tid; i < 2 * NPTS; i += 256) {
        float v = (i < NPTS) ? __int_as_float(g_rowmin[bc * NPTS + i])
                             : __int_as_float(g_colmin[bc * NPTS + i - NPTS]);
        m = fmaxf(m, v);
    }
    red[tid] = m;
    __syncthreads();
    for (int s = 128; s > 0; s >>= 1) {
        if (tid < s) red[tid] = fmaxf(red[tid], red[tid + s]);
        __syncthreads();
    }
    if (tid == 0) atomicAdd(out, sqrtf(red[0]) * (1.0f / BCD));
}

// ---------------- launch: forked-stream convert/GEMM pipeline ----------------
extern "C" void kernel_launch(void* const* d_in, const int* in_sizes, int n_in,
                              void* d_out, int out_size) {
    const float* x = (const float*)d_in[0];
    const float* y = (const float*)d_in[1];
    float* out = (float*)d_out;

    cudaFuncSetAttribute(hd_gemm_mma, cudaFuncAttributeMaxDynamicSharedMemorySize, DSMEM_BYTES);

    for (int i = 0; i < NCH; i++) {
        int bc0 = i * CH;
        // producer on the main (capture) stream
        hd_convert_norms<<<dim3(CH * NPTS / 2, 2), 256>>>(x, y, out, bc0);
        cudaEventRecord(hds.ev[i], 0);
        // consumer on its own stream, gated on this chunk's convert
        cudaStreamWaitEvent(hds.gs[i], hds.ev[i], 0);
        hd_gemm_mma<<<dim3(NPTS / BN, NPTS / BM, CH), 256, DSMEM_BYTES, hds.gs[i]>>>(bc0);
        cudaEventRecord(hds.done[i], hds.gs[i]);
        cudaStreamWaitEvent(0, hds.done[i], 0);
    }

    hd_reduce_kernel<<<BCD, 256>>>(out);
}

// round 14
// speedup vs baseline: 1.2760x; 1.2760x over previous
#include <cuda_runtime.h>
#include <cuda_fp16.h>
#include <cstdint>

// Problem: [B=8, C=3, N=1024, D=1024]
#define BCD    24
#define NPTS   1024
#define KDIM   1024

#define BM     128
#define BN     128
#define BKH    64              // k halves per stage (128 bytes/row)
#define NSTAGE 3
#define NKITER (KDIM / BKH)    // 16
#define ROWB   128             // smem bytes per row
#define A_BYTES (BM * ROWB)    // 16384
#define STAGE_BYTES (2 * A_BYTES)            // 32768
#define DSMEM_BYTES (NSTAGE * STAGE_BYTES)   // 98304

#define NCH    6               // pipeline chunks
#define CH     (BCD / NCH)     // 4 slices per chunk

// ---------------- scratch ----------------
__device__ __half g_xh[(size_t)BCD * NPTS * KDIM];
__device__ __half g_yh[(size_t)BCD * NPTS * KDIM];
__device__ float g_x2[BCD * NPTS];
__device__ float g_y2[BCD * NPTS];
__device__ int   g_rowmin[BCD * NPTS];
__device__ int   g_colmin[BCD * NPTS];

// ---------------- streams/events (static init: before harness checkpoints) ----
struct HdStreams {
    cudaStream_t gs[NCH];
    cudaEvent_t ev[NCH];
    cudaEvent_t done[NCH];
    HdStreams() {
        for (int i = 0; i < NCH; i++) {
            cudaStreamCreateWithFlags(&gs[i], cudaStreamNonBlocking);
            cudaEventCreateWithFlags(&ev[i], cudaEventDisableTiming);
            cudaEventCreateWithFlags(&done[i], cudaEventDisableTiming);
        }
    }
};
static HdStreams hds;

// ---------------- helpers ----------------
__device__ __forceinline__ uint32_t smem_u32(const void* p) {
    uint32_t a;
    asm("{ .reg .u64 t; cvta.to.shared.u64 t, %1; cvt.u32.u64 %0, t; }" : "=r"(a) : "l"(p));
    return a;
}
__device__ __forceinline__ void cp16(uint32_t dst, const void* src) {
    asm volatile("cp.async.cg.shared.global [%0], [%1], 16;" :: "r"(dst), "l"(src));
}
__device__ __forceinline__ void cp_commit() {
    asm volatile("cp.async.commit_group;" ::: "memory");
}
// 128B-row XOR swizzle: chunk c (16B) of row r -> c ^ (r & 7).
__device__ __forceinline__ uint32_t swz(int row, int c) {
    return (uint32_t)(row * ROWB + ((c ^ (row & 7)) << 4));
}
#define LDSM4(r0, r1, r2, r3, addr)                                          \
    asm volatile("ldmatrix.sync.aligned.m8n8.x4.shared.b16 {%0,%1,%2,%3}, [%4];" \
                 : "=r"(r0), "=r"(r1), "=r"(r2), "=r"(r3) : "r"(addr))
#define MMA16816(c, a, b)                                                    \
    asm volatile("mma.sync.aligned.m16n8k16.row.col.f32.f16.f16.f32 "        \
                 "{%0,%1,%2,%3}, {%4,%5,%6,%7}, {%8,%9}, {%0,%1,%2,%3};"     \
                 : "+f"((c)[0]), "+f"((c)[1]), "+f"((c)[2]), "+f"((c)[3])    \
                 : "r"((a)[0]), "r"((a)[1]), "r"((a)[2]), "r"((a)[3]),       \
                   "r"((b)[0]), "r"((b)[1]))

// ---------------- convert + norms + init for one chunk of CH slices ----------
// grid = (CH*NPTS/2, 2); block = 256 = 2 rows x 128 threads.
__global__ void hd_convert_norms(const float* __restrict__ x, const float* __restrict__ y,
                                 float* __restrict__ out, int bc0) {
    __shared__ float part[8];
    int tid = threadIdx.x;

    // Init this chunk's min arrays (2 entries per x-block, y==0 slice only).
    if (blockIdx.y == 0 && tid < 2) {
        int i = bc0 * NPTS + blockIdx.x * 2 + tid;
        g_rowmin[i] = 0x7F800000;
        g_colmin[i] = 0x7F800000;
        if (bc0 == 0 && blockIdx.x == 0 && tid == 0) out[0] = 0.0f;
    }

    size_t base = (size_t)bc0 * NPTS * KDIM + (size_t)blockIdx.x * 2048 + (size_t)tid * 8;
    const float* src = blockIdx.y ? y : x;
    __half* dst = blockIdx.y ? g_yh : g_xh;
    float* nrm = blockIdx.y ? g_y2 : g_x2;

    float4 v0 = *(const float4*)(src + base);
    float4 v1 = *(const float4*)(src + base + 4);
    __half2 h0 = __floats2half2_rn(v0.x, v0.y);
    __half2 h1 = __floats2half2_rn(v0.z, v0.w);
    __half2 h2 = __floats2half2_rn(v1.x, v1.y);
    __half2 h3 = __floats2half2_rn(v1.z, v1.w);
    uint4 o;
    o.x = *(uint32_t*)&h0; o.y = *(uint32_t*)&h1;
    o.z = *(uint32_t*)&h2; o.w = *(uint32_t*)&h3;
    *(uint4*)(dst + base) = o;

    float s = 0.0f;
    {
        float2 f;
        f = __half22float2(h0); s += f.x * f.x + f.y * f.y;
        f = __half22float2(h1); s += f.x * f.x + f.y * f.y;
        f = __half22float2(h2); s += f.x * f.x + f.y * f.y;
        f = __half22float2(h3); s += f.x * f.x + f.y * f.y;
    }
    #pragma unroll
    for (int off = 16; off > 0; off >>= 1)
        s += __shfl_down_sync(0xFFFFFFFFu, s, off);
    if ((tid & 31) == 0) part[tid >> 5] = s;
    __syncthreads();
    if (tid < 2) {
        float t = part[tid * 4] + part[tid * 4 + 1] + part[tid * 4 + 2] + part[tid * 4 + 3];
        nrm[bc0 * NPTS + blockIdx.x * 2 + tid] = t;
    }
}

// ---------------- stage loader ----------------
__device__ __forceinline__ void load_stage(int it, int tid, uint32_t sbase,
                                           const __half* __restrict__ gA,
                                           const __half* __restrict__ gB) {
    if (it < NKITER) {
        uint32_t sb = sbase + (it % NSTAGE) * STAGE_BYTES;
        int k0 = it * BKH;
        #pragma unroll
        for (int t = 0; t < 4; t++) {
            int idx = tid + t * 256;          // 0..1023
            int row = idx >> 3;               // 0..127
            int c = idx & 7;                  // 16B chunk (8 per row)
            cp16(sb + swz(row, c),           gA + (size_t)row * KDIM + k0 + c * 8);
            cp16(sb + A_BYTES + swz(row, c), gB + (size_t)row * KDIM + k0 + c * 8);
        }
    }
    cp_commit();
}

// ---------------- main MMA GEMM + fused min epilogue (R6 body) ----------------
__global__ void __launch_bounds__(256, 2)
hd_gemm_mma(int bc0) {
    extern __shared__ char smem[];
    __shared__ float sx2[BM], sy2[BN];
    __shared__ int sminr[BM], sminc[BN];

    int tid = threadIdx.x, lane = tid & 31, wid = tid >> 5;
    int warp_m = wid & 3, warp_n = wid >> 2;     // 4x2 warps, warp tile 32x64
    int bc = bc0 + blockIdx.z, nblk = blockIdx.y * BM, mblk = blockIdx.x * BN;
    const __half* gA = g_xh + ((size_t)bc * NPTS + nblk) * KDIM;
    const __half* gB = g_yh + ((size_t)bc * NPTS + mblk) * KDIM;
    uint32_t sbase = smem_u32(smem);

    if (tid < BM) {
        sx2[tid] = g_x2[bc * NPTS + nblk + tid];
        sy2[tid] = g_y2[bc * NPTS + mblk + tid];
        sminr[tid] = 0x7F800000;
        sminc[tid] = 0x7F800000;
    }

    float acc[2][8][4];
    #pragma unroll
    for (int mt = 0; mt < 2; mt++)
        #pragma unroll
        for (int nt = 0; nt < 8; nt++)
            #pragma unroll
            for (int e = 0; e < 4; e++) acc[mt][nt][e] = 0.0f;

    load_stage(0, tid, sbase, gA, gB);
    load_stage(1, tid, sbase, gA, gB);

    int lr = lane & 7, grp = lane >> 3;
    int arow0 = warp_m * 32 + lr + ((grp & 1) << 3);
    int brow0 = warp_n * 64 + lr + ((grp >> 1) << 3);
    int ac_x = grp >> 1;
    int bc_x = grp & 1;

    for (int i = 0; i < NKITER; i++) {
        asm volatile("cp.async.wait_group 1;" ::: "memory");
        __syncthreads();
        load_stage(i + 2, tid, sbase, gA, gB);
        uint32_t sA = sbase + (i % NSTAGE) * STAGE_BYTES;
        uint32_t sB = sA + A_BYTES;
        #pragma unroll
        for (int ks = 0; ks < 4; ks++) {
            uint32_t a[2][4], b[8][2];
            #pragma unroll
            for (int mt = 0; mt < 2; mt++) {
                int row = arow0 + mt * 16;
                uint32_t addr = sA + swz(row, ks * 2 + ac_x);
                LDSM4(a[mt][0], a[mt][1], a[mt][2], a[mt][3], addr);
            }
            #pragma unroll
            for (int bt = 0; bt < 4; bt++) {
                int row = brow0 + bt * 16;
                uint32_t addr = sB + swz(row, ks * 2 + bc_x);
                uint32_t r0, r1, r2, r3;
                LDSM4(r0, r1, r2, r3, addr);
                b[bt * 2][0] = r0;     b[bt * 2][1] = r1;
                b[bt * 2 + 1][0] = r2; b[bt * 2 + 1][1] = r3;
            }
            #pragma unroll
            for (int mt = 0; mt < 2; mt++)
                #pragma unroll
                for (int nt = 0; nt < 8; nt++)
                    MMA16816(acc[mt][nt], a[mt], b[nt]);
        }
    }

    // ---- fused epilogue: d2 + row/col mins ----
    int g = lane >> 2, l = lane & 3;
    float xr[4], yc[16];
    #pragma unroll
    for (int r = 0; r < 4; r++)
        xr[r] = sx2[warp_m * 32 + (r >> 1) * 16 + ((r & 1) << 3) + g];
    #pragma unroll
    for (int c = 0; c < 16; c++)
        yc[c] = sy2[warp_n * 64 + (c >> 1) * 8 + l * 2 + (c & 1)];

    float rmin[4], cmin[16];
    #pragma unroll
    for (int r = 0; r < 4; r++) rmin[r] = 3.4e38f;
    #pragma unroll
    for (int c = 0; c < 16; c++) cmin[c] = 3.4e38f;

    #pragma unroll
    for (int mt = 0; mt < 2; mt++)
        #pragma unroll
        for (int nt = 0; nt < 8; nt++)
            #pragma unroll
            for (int e = 0; e < 4; e++) {
                int rid = mt * 2 + (e >> 1);
                int cid = nt * 2 + (e & 1);
                float d2 = fmaxf(xr[rid] + yc[cid] - 2.0f * acc[mt][nt][e], 0.0f);
                rmin[rid] = fminf(rmin[rid], d2);
                cmin[cid] = fminf(cmin[cid], d2);
            }

    #pragma unroll
    for (int r = 0; r < 4; r++) {
        rmin[r] = fminf(rmin[r], __shfl_xor_sync(0xFFFFFFFFu, rmin[r], 1));
        rmin[r] = fminf(rmin[r], __shfl_xor_sync(0xFFFFFFFFu, rmin[r], 2));
    }
    #pragma unroll
    for (int c = 0; c < 16; c++) {
        cmin[c] = fminf(cmin[c], __shfl_xor_sync(0xFFFFFFFFu, cmin[c], 4));
        cmin[c] = fminf(cmin[c], __shfl_xor_sync(0xFFFFFFFFu, cmin[c], 8));
        cmin[c] = fminf(cmin[c], __shfl_xor_sync(0xFFFFFFFFu, cmin[c], 16));
    }
    if (l == 0) {
        #pragma unroll
        for (int r = 0; r < 4; r++)
            atomicMin(&sminr[warp_m * 32 + (r >> 1) * 16 + ((r & 1) << 3) + g],
                      __float_as_int(rmin[r]));
    }
    if (g == 0) {
        #pragma unroll
        for (int c = 0; c < 16; c++)
            atomicMin(&sminc[warp_n * 64 + (c >> 1) * 8 + l * 2 + (c & 1)],
                      __float_as_int(cmin[c]));
    }
    __syncthreads();
    if (tid < BM) {
        atomicMin(&g_rowmin[bc * NPTS + nblk + tid], sminr[tid]);
        atomicMin(&g_colmin[bc * NPTS + mblk + tid], sminc[tid]);
    }
}

// ---------------- final reduction: one block per (b,c) ----------------
__global__ void hd_reduce_kernel(float* __restrict__ out) {
    __shared__ float red[256];
    int bc = blockIdx.x, tid = threadIdx.x;
    float m = 0.0f;
    for (int i = tid; i < 2 * NPTS; i += 256) {
        float v = (i < NPTS) ? __int_as_float(g_rowmin[bc * NPTS + i])
                             : __int_as_float(g_colmin[bc * NPTS + i - NPTS]);
        m = fmaxf(m, v);
    }
    red[tid] = m;
    __syncthreads();
    for (int s = 128; s > 0; s >>= 1) {
        if (tid < s) red[tid] = fmaxf(red[tid], red[tid + s]);
        __syncthreads();
    }
    if (tid == 0) atomicAdd(out, sqrtf(red[0]) * (1.0f / BCD));
}

// ---------------- launch: forked-stream convert/GEMM pipeline ----------------
extern "C" void kernel_launch(void* const* d_in, const int* in_sizes, int n_in,
                              void* d_out, int out_size) {
    const float* x = (const float*)d_in[0];
    const float* y = (const float*)d_in[1];
    float* out = (float*)d_out;

    cudaFuncSetAttribute(hd_gemm_mma, cudaFuncAttributeMaxDynamicSharedMemorySize, DSMEM_BYTES);

    // Issue all converts back-to-back on stream 0; each GEMM chunk runs on its
    // own stream gated only on its chunk's convert. Join AFTER the loop.
    for (int i = 0; i < NCH; i++) {
        int bc0 = i * CH;
        hd_convert_norms<<<dim3(CH * NPTS / 2, 2), 256>>>(x, y, out, bc0);
        cudaEventRecord(hds.ev[i], 0);
        cudaStreamWaitEvent(hds.gs[i], hds.ev[i], 0);
        hd_gemm_mma<<<dim3(NPTS / BN, NPTS / BM, CH), 256, DSMEM_BYTES, hds.gs[i]>>>(bc0);
        cudaEventRecord(hds.done[i], hds.gs[i]);
    }
    for (int i = 0; i < NCH; i++)
        cudaStreamWaitEvent(0, hds.done[i], 0);

    hd_reduce_kernel<<<BCD, 256>>>(out);
}